// round 16
// baseline (speedup 1.0000x reference)
#include <cuda_runtime.h>
#include <cuda_bf16.h>
#include <cstdint>

#define TT 8
#define PX 1024
typedef __nv_bfloat16 bf16;

__device__ __align__(16) bf16  g_ft[(size_t)64 * 2 * PX * 128];
__device__ __align__(16) bf16  g_xs1[(size_t)64 * 2 * PX * 128];
__device__ __align__(16) bf16  g_hb[(size_t)32 * 2 * PX * 64];
__device__ __align__(16) float g_cb[(size_t)32 * PX * 64];
__device__ __align__(16) float g_g0[(size_t)128 * PX * 256];
__device__ __align__(16) float g_g1[(size_t)72 * PX * 256];
__device__ __align__(16) float g_lastb[(size_t)8 * PX * 128];
__device__ __align__(16) bf16  g_wpk[(size_t)4 * 589824 + (size_t)3 * 294912];
__device__ __align__(16) float g_bc[4 * 256];
__device__ const float* g_wptr[8];
__device__ const float* g_biptr[4];
__device__ const float* g_bhptr[4];

__device__ __forceinline__ uint32_t smem_u32(const void* p) {
    uint32_t a;
    asm("{ .reg .u64 t; cvta.to.shared.u64 t, %1; cvt.u32.u64 %0, t; }" : "=r"(a) : "l"(p));
    return a;
}
__device__ __forceinline__ void ldsm4(uint32_t* r, uint32_t a) {
    asm volatile("ldmatrix.sync.aligned.m8n8.x4.shared.b16 {%0,%1,%2,%3}, [%4];"
        : "=r"(r[0]), "=r"(r[1]), "=r"(r[2]), "=r"(r[3]) : "r"(a));
}
__device__ __forceinline__ void mma16816(float* d, const uint32_t* a, const uint32_t* b) {
    asm volatile("mma.sync.aligned.m16n8k16.row.col.f32.bf16.bf16.f32 "
        "{%0,%1,%2,%3},{%4,%5,%6,%7},{%8,%9},{%0,%1,%2,%3};"
        : "+f"(d[0]), "+f"(d[1]), "+f"(d[2]), "+f"(d[3])
        : "r"(a[0]), "r"(a[1]), "r"(a[2]), "r"(a[3]), "r"(b[0]), "r"(b[1]));
}
__device__ __forceinline__ void cp16(uint32_t d, const void* s, uint32_t sz) {
    asm volatile("cp.async.cg.shared.global [%0], [%1], 16, %2;" :: "r"(d), "l"(s), "r"(sz) : "memory");
}
__device__ __forceinline__ void cp16f(uint32_t d, const void* s) {
    asm volatile("cp.async.cg.shared.global [%0], [%1], 16;" :: "r"(d), "l"(s) : "memory");
}
__device__ __forceinline__ void cp_commit() { asm volatile("cp.async.commit_group;" ::: "memory"); }
__device__ __forceinline__ void cp_wait0() { asm volatile("cp.async.wait_group 0;" ::: "memory"); }
__device__ __forceinline__ void cp_wait1() { asm volatile("cp.async.wait_group 1;" ::: "memory"); }
__device__ __forceinline__ float sigf(float x) { return 1.f / (1.f + __expf(-x)); }

__global__ void setptr_k(const float* w0, const float* w1, const float* w2, const float* w3,
                         const float* w4, const float* w5, const float* w6,
                         const float* bi0, const float* bi1, const float* bi2, const float* bi3,
                         const float* bh0, const float* bh1, const float* bh2, const float* bh3)
{
    g_wptr[0] = w0; g_wptr[1] = w1; g_wptr[2] = w2; g_wptr[3] = w3;
    g_wptr[4] = w4; g_wptr[5] = w5; g_wptr[6] = w6;
    g_biptr[0] = bi0; g_biptr[1] = bi1; g_biptr[2] = bi2; g_biptr[3] = bi3;
    g_bhptr[0] = bh0; g_bhptr[1] = bh1; g_bhptr[2] = bh2; g_bhptr[3] = bh3;
}

__global__ void repack_all(bf16* __restrict__ wdst, float* __restrict__ bc)
{
    int s = blockIdx.y;
    int cin = (s < 4) ? 128 : 64;
    int tot = 256 * cin * 9;
    int idx = blockIdx.x * 256 + threadIdx.x;
    bf16* dst = (s < 4) ? wdst + (size_t)s * 589824
                        : wdst + (size_t)4 * 589824 + (size_t)(s - 4) * 294912;
    if (idx < tot) {
        const float* w = g_wptr[s];
        int k = idx % 9, rest = idx / 9;
        int ci = rest % cin, g = rest / cin;
        int gp = (g & 63) * 4 + (g >> 6);
        float v = w[idx];
        bf16 hi = __float2bfloat16(v);
        bf16 lo = __float2bfloat16(v - __bfloat162float(hi));
        size_t o = ((size_t)k * 256 + gp) * cin + ci;
        dst[o] = hi;
        dst[(size_t)9 * 256 * cin + o] = lo;
    }
    if (s < 4 && blockIdx.x == 0 && threadIdx.x < 256) {
        int g = threadIdx.x;
        bc[s * 256 + (g & 63) * 4 + (g >> 6)] = g_biptr[s][g] + g_bhptr[s][g];
    }
}

__global__ void feat_tr_k(const float* __restrict__ f)
{
    __shared__ float s[32][257];
    int img = blockIdx.x, cbk = blockIdx.y, pb = blockIdx.z, tid = threadIdx.x;
    int b = img & 7, t = img >> 3;
    const float* src = f + ((size_t)(b * TT + t) * 128 + cbk * 32) * PX + pb * 256;
#pragma unroll 8
    for (int r = 0; r < 32; r++) s[r][tid] = src[(size_t)r * PX + tid];
    __syncthreads();
    int ci = tid & 31, pl = tid >> 5;
    bf16* dh = g_ft + (size_t)(img * 2) * PX * 128;
    bf16* dl = dh + (size_t)PX * 128;
#pragma unroll 8
    for (int wv = 0; wv < 32; wv++) {
        int p = pb * 256 + wv * 8 + pl;
        float v = s[ci][wv * 8 + pl];
        bf16 hi = __float2bfloat16(v);
        dh[(size_t)p * 128 + cbk * 32 + ci] = hi;
        dl[(size_t)p * 128 + cbk * 32 + ci] = __float2bfloat16(v - __bfloat162float(hi));
    }
}

// ===== ih conv, M-split tiles: CTA 64px x 128 gates, 3 CTAs/SM ====================
#define MSTAGE 24576
template <int MODE>   // 0: L0 ih (z=dir*64+t*8+b), 2: L1 ih (z=slot)
__global__ void __launch_bounds__(256, 3)
conv_ihm(const bf16* __restrict__ act, const bf16* __restrict__ wpa,
         const bf16* __restrict__ wpb, const float* __restrict__ biasa,
         const float* __restrict__ biasb, float* __restrict__ gB)
{
    extern __shared__ __align__(16) char sm[];
    const int tid = threadIdx.x, lane = tid & 31, wid = tid >> 5;
    const int wM = wid & 1, wN = wid >> 1;        // warp: 32px x 32 gates
    const int ghalf = blockIdx.x, tile = blockIdx.y, z = blockIdx.z;

    const bf16* wp = wpa;
    const float* bias = biasa;
    int slot = z;
    if (MODE == 0) { int dir = z >> 6; slot = z & 63; if (dir) { wp = wpb; bias = biasb; } }

    const size_t actps = (size_t)PX * 128;
    const bf16* aimg_p = act + (size_t)slot * 2 * actps;
    const size_t wps = (size_t)9 * 256 * 128;
    const uint32_t su = smem_u32(sm);

    float acc[2][4][4];
#pragma unroll
    for (int a = 0; a < 2; a++)
#pragma unroll
        for (int n = 0; n < 4; n++)
#pragma unroll
            for (int c = 0; c < 4; c++) acc[a][n][c] = 0.f;

    const int NIT = 54;
    const int gpxA = tile * 64 + (tid & 63);

    auto issue = [&](int it) {
        int buf = it % 3;
        int term = it / 18, rem = it - term * 18;
        int k = rem >> 1, half = rem & 1;
        int pa = (term == 1), pbw = (term == 2);
        uint32_t base = su + buf * MSTAGE;
        if (tid < 64) {
            int r = tid;
            int ys = (gpxA >> 5) + k / 3 - 1, xsv = (gpxA & 31) + k % 3 - 1;
            bool v = ((unsigned)ys < 32u) && ((unsigned)xsv < 32u);
            const char* asrc = (const char*)(aimg_p + (size_t)pa * actps +
                               (v ? (size_t)(ys * 32 + xsv) * 128 : (size_t)0) + half * 64);
            uint32_t sz = v ? 16u : 0u;
            uint32_t dst = base + r * 128;
#pragma unroll
            for (int j = 0; j < 8; j++)
                cp16(dst + ((j ^ (r & 7)) * 16), asrc + j * 16, sz);
        } else if (tid < 192) {
            int r = tid - 64;
            const char* bsrc = (const char*)(wp + (size_t)pbw * wps +
                               ((size_t)k * 256 + ghalf * 128 + r) * 128 + half * 64);
            uint32_t dst = base + 8192 + r * 128;
#pragma unroll
            for (int j = 0; j < 8; j++)
                cp16f(dst + ((j ^ (r & 7)) * 16), bsrc + j * 16);
        }
        cp_commit();
    };

    const int aro = (lane & 7) + 8 * ((lane >> 3) & 1), acs = (lane >> 4) & 1;
    const int bro = (lane & 7) + 8 * ((lane >> 4) & 1), bcs = (lane >> 3) & 1;

    issue(0);
    issue(1);
    for (int it = 0; it < NIT; it++) {
        if (it < NIT - 1) cp_wait1(); else cp_wait0();
        __syncthreads();
        if (it + 2 < NIT) issue(it + 2);
        uint32_t sa = su + (it % 3) * MSTAGE, sb = sa + 8192;
#pragma unroll
        for (int s = 0; s < 4; s++) {
            uint32_t af[2][4];
#pragma unroll
            for (int mi = 0; mi < 2; mi++) {
                int row = wM * 32 + mi * 16 + aro;
                ldsm4(af[mi], sa + row * 128 + ((2 * s + acs) ^ (row & 7)) * 16);
            }
#pragma unroll
            for (int np = 0; np < 2; np++) {
                uint32_t bfr[4];
                int row = wN * 32 + np * 16 + bro;
                ldsm4(bfr, sb + row * 128 + ((2 * s + bcs) ^ (row & 7)) * 16);
#pragma unroll
                for (int mi = 0; mi < 2; mi++) {
                    mma16816(acc[mi][np * 2],     af[mi], bfr);
                    mma16816(acc[mi][np * 2 + 1], af[mi], bfr + 2);
                }
            }
        }
    }
    __syncthreads();

    // stage accs: 64 rows x 128 cols, stride 130
    float* st = (float*)sm;
    const int r0 = wM * 32 + (lane >> 2), c0 = wN * 32 + (lane & 3) * 2;
#pragma unroll
    for (int mi = 0; mi < 2; mi++)
#pragma unroll
        for (int ni = 0; ni < 4; ni++) {
            int r = r0 + mi * 16, c = c0 + ni * 8;
            *(float2*)(st + r * 130 + c)       = *(float2*)acc[mi][ni];
            *(float2*)(st + (r + 8) * 130 + c) = *(float2*)(acc[mi][ni] + 2);
        }
    __syncthreads();

    float* gout = gB + (size_t)z * PX * 256;
    float4 bq = *(const float4*)(bias + ghalf * 128 + lane * 4);
#pragma unroll 1
    for (int it = 0; it < 8; it++) {
        int px = wid + 8 * it;
        float2 a01 = *(float2*)(st + px * 130 + lane * 4);
        float2 a23 = *(float2*)(st + px * 130 + lane * 4 + 2);
        float4 o = { a01.x + bq.x, a01.y + bq.y, a23.x + bq.z, a23.y + bq.w };
        *(float4*)(gout + (size_t)(tile * 64 + px) * 256 + ghalf * 128 + lane * 4) = o;
    }
}

// ===== hh conv + fused cell (round-12 proven): CTA 128px x 128g, 2 CTAs/SM ========
template <int MODE>   // 1: L0 hh (z=dir*8+b), 3: L1f hh (z=b)
__global__ void __launch_bounds__(256, 2)
conv_hh(const bf16* __restrict__ act, const bf16* __restrict__ wpa,
        const bf16* __restrict__ wpb, float* __restrict__ gB,
        float* __restrict__ cB, bf16* __restrict__ hB,
        bf16* __restrict__ xsB, float* __restrict__ lastB, int t)
{
    extern __shared__ __align__(16) char sm[];
    const int tid = threadIdx.x, lane = tid & 31, wid = tid >> 5;
    const int wM = wid & 3, wN = wid >> 2;
    const int ghalf = blockIdx.x, tile = blockIdx.y, z = blockIdx.z;

    const bf16* wp = wpa;
    int aimg, xslot = 0, choff = 0;
    if (MODE == 1) {
        int dir = z >> 3, b_ = z & 7;
        if (dir) wp = wpb;
        int teff = dir ? 7 - t : t;
        aimg = dir * 64 + teff * 8 + b_;
        xslot = teff * 8 + b_; choff = dir * 64;
    } else { aimg = t * 8 + z; }

    const size_t actps = (size_t)PX * 64;
    const bf16* aimg_p = act + (size_t)z * 2 * actps;
    const size_t wps = (size_t)9 * 256 * 64;
    const uint32_t su = smem_u32(sm);

    float acc[2][8][4];
#pragma unroll
    for (int a = 0; a < 2; a++)
#pragma unroll
        for (int n = 0; n < 8; n++)
#pragma unroll
            for (int c = 0; c < 4; c++) acc[a][n][c] = 0.f;

    const int NIT = 27;
    const int lrow = tid >> 1, seg = (tid & 1) * 64;
    const int gpxA = tile * 128 + lrow;

    auto issue = [&](int it) {
        int buf = it % 3;
        int term = it / 9, k = it - term * 9;
        int pa = (term == 1), pbw = (term == 2);
        int ys = (gpxA >> 5) + k / 3 - 1, xsv = (gpxA & 31) + k % 3 - 1;
        bool v = ((unsigned)ys < 32u) && ((unsigned)xsv < 32u);
        const char* asrc = (const char*)(aimg_p + (size_t)pa * actps +
                           (v ? (size_t)(ys * 32 + xsv) * 64 : (size_t)0)) + seg;
        const char* bsrc = (const char*)(wp + (size_t)pbw * wps +
                           ((size_t)k * 256 + ghalf * 128 + lrow) * 64) + seg;
        uint32_t ab = su + buf * 32768 + lrow * 128;
        uint32_t bb_ = ab + 16384;
        uint32_t sz = v ? 16u : 0u;
#pragma unroll
        for (int j = 0; j < 4; j++) {
            uint32_t off = seg + j * 16;
            uint32_t swz = off ^ ((lrow & 7) << 4);
            cp16(ab + swz, asrc + j * 16, sz);
            cp16f(bb_ + swz, bsrc + j * 16);
        }
        cp_commit();
    };

    const int aro = (lane & 7) + 8 * ((lane >> 3) & 1), acs = (lane >> 4) & 1;
    const int bro = (lane & 7) + 8 * ((lane >> 4) & 1), bcs = (lane >> 3) & 1;

    issue(0);
    issue(1);
    for (int it = 0; it < NIT; it++) {
        if (it < NIT - 1) cp_wait1(); else cp_wait0();
        __syncthreads();
        if (it + 2 < NIT) issue(it + 2);
        uint32_t sa = su + (it % 3) * 32768, sb = sa + 16384;
#pragma unroll
        for (int s = 0; s < 4; s++) {
            uint32_t af[2][4];
#pragma unroll
            for (int mi = 0; mi < 2; mi++) {
                int row = wM * 32 + mi * 16 + aro;
                ldsm4(af[mi], sa + row * 128 + ((2 * s + acs) ^ (row & 7)) * 16);
            }
#pragma unroll
            for (int np = 0; np < 4; np++) {
                uint32_t bfr[4];
                int row = wN * 64 + np * 16 + bro;
                ldsm4(bfr, sb + row * 128 + ((2 * s + bcs) ^ (row & 7)) * 16);
#pragma unroll
                for (int mi = 0; mi < 2; mi++) {
                    mma16816(acc[mi][np * 2],     af[mi], bfr);
                    mma16816(acc[mi][np * 2 + 1], af[mi], bfr + 2);
                }
            }
        }
    }
    __syncthreads();

    float* st = (float*)sm;
    const int r0 = wM * 32 + (lane >> 2), c0 = wN * 64 + (lane & 3) * 2;
#pragma unroll
    for (int mi = 0; mi < 2; mi++)
#pragma unroll
        for (int ni = 0; ni < 8; ni++) {
            int r = r0 + mi * 16, c = c0 + ni * 8;
            *(float2*)(st + r * 130 + c)       = *(float2*)acc[mi][ni];
            *(float2*)(st + (r + 8) * 130 + c) = *(float2*)(acc[mi][ni] + 2);
        }
    __syncthreads();

    const int gch = ghalf * 32 + lane;
#pragma unroll 1
    for (int it = 0; it < 16; it++) {
        int px = wid + 8 * it;
        int gpx = tile * 128 + px;
        float2 a01 = *(float2*)(st + px * 130 + lane * 4);
        float2 a23 = *(float2*)(st + px * 130 + lane * 4 + 2);
        float4 g4 = *(const float4*)(gB + ((size_t)aimg * PX + gpx) * 256 + gch * 4);
        float i_ = a01.x + g4.x, f_ = a01.y + g4.y;
        float g_ = a23.x + g4.z, o_ = a23.y + g4.w;
        size_t ci = ((size_t)z * PX + gpx) * 64 + gch;
        float cp = cB[ci];
        float cn = sigf(f_) * cp + sigf(i_) * tanhf(g_);
        float hn = sigf(o_) * tanhf(cn);
        cB[ci] = cn;
        bf16 hh_ = __float2bfloat16(hn);
        bf16 hl_ = __float2bfloat16(hn - __bfloat162float(hh_));
        size_t hi_ = ((size_t)z * 2 * PX + gpx) * 64 + gch;
        hB[hi_] = hh_;
        hB[hi_ + (size_t)PX * 64] = hl_;
        if (MODE == 1) {
            size_t xb = ((size_t)(xslot * 2) * PX + gpx) * 128 + choff + gch;
            xsB[xb] = hh_;
            xsB[xb + (size_t)PX * 128] = hl_;
        }
        if (MODE == 3 && lastB)
            lastB[((size_t)z * PX + gpx) * 128 + gch] = hn;
    }
}

__global__ void cell_k(const float* __restrict__ gih, float* __restrict__ cB,
                       bf16* __restrict__ hB, bf16* __restrict__ xsB,
                       float* __restrict__ lastB, int mode, int lco, int n)
{
    int i = blockIdx.x * 256 + threadIdx.x;
    if (i >= n) return;
    int ch = i & 63, px = (i >> 6) & 1023, im = i >> 16;
    int gslot = im, xslot = 0, choff = 0;
    if (mode == 0) {
        int dir = im >> 3, b = im & 7;
        int teff = dir ? 7 : 0;
        gslot = dir * 64 + teff * 8 + b;
        xslot = teff * 8 + b; choff = dir * 64;
    }
    float4 g4 = *(const float4*)(gih + ((size_t)gslot * PX + px) * 256 + ch * 4);
    float cn = sigf(g4.x) * tanhf(g4.z);
    float hn = sigf(g4.w) * tanhf(cn);
    cB[i] = cn;
    bf16 hh_ = __float2bfloat16(hn);
    bf16 hl_ = __float2bfloat16(hn - __bfloat162float(hh_));
    size_t hb_ = ((size_t)im * 2 * PX + px) * 64 + ch;
    hB[hb_] = hh_;
    hB[hb_ + (size_t)PX * 64] = hl_;
    if (xsB) {
        size_t xb = ((size_t)(xslot * 2) * PX + px) * 128 + choff + ch;
        xsB[xb] = hh_;
        xsB[xb + (size_t)PX * 128] = hl_;
    }
    if (lastB) lastB[((size_t)im * PX + px) * 128 + lco + ch] = hn;
}

__global__ void __launch_bounds__(256) head_k(const float* __restrict__ last,
                                              const float* __restrict__ w,
                                              const float* __restrict__ bias,
                                              float* __restrict__ out)
{
    __shared__ float sw[8192];
    __shared__ float sb[64];
    int b = blockIdx.x, pb = blockIdx.y, tid = threadIdx.x;
    for (int i = tid; i < 8192; i += 256) sw[i] = w[i];
    if (tid < 64) sb[tid] = bias[tid];
    __syncthreads();
    int px = pb * 256 + tid;
    const float4* lrow = (const float4*)(last + ((size_t)b * PX + px) * 128);
    float4 lv[32];
#pragma unroll
    for (int j = 0; j < 32; j++) lv[j] = lrow[j];
#pragma unroll 1
    for (int o = 0; o < 64; o++) {
        const float4* wr = (const float4*)(sw + o * 128);
        float acc = sb[o];
#pragma unroll
        for (int j = 0; j < 32; j++) {
            float4 wv = wr[j];
            acc += lv[j].x * wv.x + lv[j].y * wv.y + lv[j].z * wv.z + lv[j].w * wv.w;
        }
        out[((size_t)b * 64 + o) * PX + px] = fmaxf(acc, 0.f);
    }
}

extern "C" void kernel_launch(void* const* d_in, const int* in_sizes, int n_in,
                              void* d_out, int out_size)
{
    const float* features = (const float*)d_in[0];
    const float* w_out = (const float*)d_in[17];
    const float* b_out = (const float*)d_in[18];
    float* out = (float*)d_out;

    bf16 *ft, *xs1, *hb, *wpk;
    float *cb, *g0, *g1, *last, *bc;
    cudaGetSymbolAddress((void**)&ft, g_ft);
    cudaGetSymbolAddress((void**)&xs1, g_xs1);
    cudaGetSymbolAddress((void**)&hb, g_hb);
    cudaGetSymbolAddress((void**)&cb, g_cb);
    cudaGetSymbolAddress((void**)&g0, g_g0);
    cudaGetSymbolAddress((void**)&g1, g_g1);
    cudaGetSymbolAddress((void**)&last, g_lastb);
    cudaGetSymbolAddress((void**)&wpk, g_wpk);
    cudaGetSymbolAddress((void**)&bc, g_bc);

    bf16* wih[4]; bf16* whh[3];
    for (int s = 0; s < 4; s++) wih[s] = wpk + (size_t)s * 589824;
    for (int s = 0; s < 3; s++) whh[s] = wpk + (size_t)4 * 589824 + (size_t)s * 294912;

    const int DSMEM = 3 * 32768;
    const int MSMEM = 3 * MSTAGE;   // 73728 (epilogue needs 64*130*4 = 33280)
    cudaFuncSetAttribute(conv_ihm<0>, cudaFuncAttributeMaxDynamicSharedMemorySize, MSMEM);
    cudaFuncSetAttribute(conv_ihm<2>, cudaFuncAttributeMaxDynamicSharedMemorySize, MSMEM);
    cudaFuncSetAttribute(conv_hh<1>,  cudaFuncAttributeMaxDynamicSharedMemorySize, DSMEM);
    cudaFuncSetAttribute(conv_hh<3>,  cudaFuncAttributeMaxDynamicSharedMemorySize, DSMEM);

    setptr_k<<<1, 1>>>((const float*)d_in[1], (const float*)d_in[5],
                       (const float*)d_in[9], (const float*)d_in[13],
                       (const float*)d_in[2], (const float*)d_in[6],
                       (const float*)d_in[10],
                       (const float*)d_in[3], (const float*)d_in[7],
                       (const float*)d_in[11], (const float*)d_in[15],
                       (const float*)d_in[4], (const float*)d_in[8],
                       (const float*)d_in[12], (const float*)d_in[16]);
    repack_all<<<dim3(1152, 7), 256>>>(wpk, bc);
    feat_tr_k<<<dim3(64, 4, 4), 256>>>(features);

    const size_t CS = (size_t)PX * 64;
    const size_t HS = (size_t)2 * PX * 64;
    const size_t IMGZ = (size_t)PX * 256;
    const int N16 = 16 * PX * 64, N8 = 8 * PX * 64;

    // ===== layer 0 =====
    conv_ihm<0><<<dim3(2, 16, 128), 256, MSMEM>>>(ft, wih[0], wih[1], bc, bc + 256, g0);
    cell_k<<<N16 / 256, 256>>>(g0, cb, hb, xs1, nullptr, 0, 0, N16);
    for (int t = 1; t < TT; t++)
        conv_hh<1><<<dim3(2, 8, 16), 256, DSMEM>>>(
            hb, whh[0], whh[1], g0, cb, hb, xs1, nullptr, t);

    // ===== layer 1 ih: forward all t; reverse only t=7 =====
    conv_ihm<2><<<dim3(2, 16, 64), 256, MSMEM>>>(
        xs1, wih[2], nullptr, bc + 512, nullptr, g1);
    conv_ihm<2><<<dim3(2, 16, 8), 256, MSMEM>>>(
        xs1 + (size_t)56 * 2 * PX * 128, wih[3], nullptr, bc + 768, nullptr,
        g1 + 64 * IMGZ);

    cell_k<<<N8 / 256, 256>>>(g1 + 64 * IMGZ, cb + 16 * CS, hb + 16 * HS,
                              nullptr, last, 1, 64, N8);
    cell_k<<<N8 / 256, 256>>>(g1, cb + 24 * CS, hb + 24 * HS, nullptr, nullptr, 1, 0, N8);
    for (int t = 1; t < TT; t++)
        conv_hh<3><<<dim3(2, 8, 8), 256, DSMEM>>>(
            hb + 24 * HS, whh[2], nullptr, g1,
            cb + 24 * CS, hb + 24 * HS, nullptr, (t == TT - 1) ? last : nullptr, t);

    head_k<<<dim3(8, 4), 256>>>(last, w_out, b_out, out);
}

// round 17
// speedup vs baseline: 1.3285x; 1.3285x over previous
#include <cuda_runtime.h>
#include <cuda_bf16.h>
#include <cstdint>

#define TT 8
#define PX 1024
typedef __nv_bfloat16 bf16;

__device__ __align__(16) bf16  g_ft[(size_t)64 * 2 * PX * 128];
__device__ __align__(16) bf16  g_xs1[(size_t)64 * 2 * PX * 128];
__device__ __align__(16) bf16  g_hb[(size_t)32 * 2 * PX * 64];
__device__ __align__(16) float g_cb[(size_t)32 * PX * 64];
__device__ __align__(16) float g_g0[(size_t)128 * PX * 256];
__device__ __align__(16) float g_g1[(size_t)72 * PX * 256];
__device__ __align__(16) float g_lastb[(size_t)8 * PX * 128];
__device__ __align__(16) bf16  g_wpk[(size_t)4 * 589824 + (size_t)3 * 294912];
__device__ __align__(16) float g_bc[4 * 256];
__device__ const float* g_wptr[8];
__device__ const float* g_biptr[4];
__device__ const float* g_bhptr[4];

__device__ __forceinline__ uint32_t smem_u32(const void* p) {
    uint32_t a;
    asm("{ .reg .u64 t; cvta.to.shared.u64 t, %1; cvt.u32.u64 %0, t; }" : "=r"(a) : "l"(p));
    return a;
}
__device__ __forceinline__ void ldsm4(uint32_t* r, uint32_t a) {
    asm volatile("ldmatrix.sync.aligned.m8n8.x4.shared.b16 {%0,%1,%2,%3}, [%4];"
        : "=r"(r[0]), "=r"(r[1]), "=r"(r[2]), "=r"(r[3]) : "r"(a));
}
__device__ __forceinline__ void mma16816(float* d, const uint32_t* a, const uint32_t* b) {
    asm volatile("mma.sync.aligned.m16n8k16.row.col.f32.bf16.bf16.f32 "
        "{%0,%1,%2,%3},{%4,%5,%6,%7},{%8,%9},{%0,%1,%2,%3};"
        : "+f"(d[0]), "+f"(d[1]), "+f"(d[2]), "+f"(d[3])
        : "r"(a[0]), "r"(a[1]), "r"(a[2]), "r"(a[3]), "r"(b[0]), "r"(b[1]));
}
__device__ __forceinline__ void cp16(uint32_t d, const void* s, uint32_t sz) {
    asm volatile("cp.async.cg.shared.global [%0], [%1], 16, %2;" :: "r"(d), "l"(s), "r"(sz) : "memory");
}
__device__ __forceinline__ void cp16f(uint32_t d, const void* s) {
    asm volatile("cp.async.cg.shared.global [%0], [%1], 16;" :: "r"(d), "l"(s) : "memory");
}
__device__ __forceinline__ void cp_commit() { asm volatile("cp.async.commit_group;" ::: "memory"); }
__device__ __forceinline__ void cp_wait0() { asm volatile("cp.async.wait_group 0;" ::: "memory"); }
__device__ __forceinline__ void cp_wait1() { asm volatile("cp.async.wait_group 1;" ::: "memory"); }
__device__ __forceinline__ float sigf(float x) { return 1.f / (1.f + __expf(-x)); }

__global__ void setptr_k(const float* w0, const float* w1, const float* w2, const float* w3,
                         const float* w4, const float* w5, const float* w6,
                         const float* bi0, const float* bi1, const float* bi2, const float* bi3,
                         const float* bh0, const float* bh1, const float* bh2, const float* bh3)
{
    g_wptr[0] = w0; g_wptr[1] = w1; g_wptr[2] = w2; g_wptr[3] = w3;
    g_wptr[4] = w4; g_wptr[5] = w5; g_wptr[6] = w6;
    g_biptr[0] = bi0; g_biptr[1] = bi1; g_biptr[2] = bi2; g_biptr[3] = bi3;
    g_bhptr[0] = bh0; g_bhptr[1] = bh1; g_bhptr[2] = bh2; g_bhptr[3] = bh3;
}

__global__ void repack_all(bf16* __restrict__ wdst, float* __restrict__ bc)
{
    int s = blockIdx.y;
    int cin = (s < 4) ? 128 : 64;
    int tot = 256 * cin * 9;
    int idx = blockIdx.x * 256 + threadIdx.x;
    bf16* dst = (s < 4) ? wdst + (size_t)s * 589824
                        : wdst + (size_t)4 * 589824 + (size_t)(s - 4) * 294912;
    if (idx < tot) {
        const float* w = g_wptr[s];
        int k = idx % 9, rest = idx / 9;
        int ci = rest % cin, g = rest / cin;
        int gp = (g & 63) * 4 + (g >> 6);
        float v = w[idx];
        bf16 hi = __float2bfloat16(v);
        bf16 lo = __float2bfloat16(v - __bfloat162float(hi));
        size_t o = ((size_t)k * 256 + gp) * cin + ci;
        dst[o] = hi;
        dst[(size_t)9 * 256 * cin + o] = lo;
    }
    if (s < 4 && blockIdx.x == 0 && threadIdx.x < 256) {
        int g = threadIdx.x;
        bc[s * 256 + (g & 63) * 4 + (g >> 6)] = g_biptr[s][g] + g_bhptr[s][g];
    }
}

__global__ void feat_tr_k(const float* __restrict__ f)
{
    __shared__ float s[32][257];
    int img = blockIdx.x, cbk = blockIdx.y, pb = blockIdx.z, tid = threadIdx.x;
    int b = img & 7, t = img >> 3;
    const float* src = f + ((size_t)(b * TT + t) * 128 + cbk * 32) * PX + pb * 256;
#pragma unroll 8
    for (int r = 0; r < 32; r++) s[r][tid] = src[(size_t)r * PX + tid];
    __syncthreads();
    int ci = tid & 31, pl = tid >> 5;
    bf16* dh = g_ft + (size_t)(img * 2) * PX * 128;
    bf16* dl = dh + (size_t)PX * 128;
#pragma unroll 8
    for (int wv = 0; wv < 32; wv++) {
        int p = pb * 256 + wv * 8 + pl;
        float v = s[ci][wv * 8 + pl];
        bf16 hi = __float2bfloat16(v);
        dh[(size_t)p * 128 + cbk * 32 + ci] = hi;
        dl[(size_t)p * 128 + cbk * 32 + ci] = __float2bfloat16(v - __bfloat162float(hi));
    }
}

// ===== R12 proven conv: CTA 128px x 128 gates, 2 CTAs/SM ==========================
// MODE 0: L0 ih. MODE 2: L1 ih. MODE 1: L0 hh + fused cell. MODE 3: L1f hh + cell.
template <int CIN, int MODE>
__global__ void __launch_bounds__(256, 2)
conv_hmma(const bf16* __restrict__ act, const bf16* __restrict__ wpa,
          const bf16* __restrict__ wpb, const float* __restrict__ biasa,
          const float* __restrict__ biasb, float* __restrict__ gB,
          float* __restrict__ cB, bf16* __restrict__ hB,
          bf16* __restrict__ xsB, float* __restrict__ lastB, int t)
{
    extern __shared__ __align__(16) char sm[];
    const int tid = threadIdx.x, lane = tid & 31, wid = tid >> 5;
    const int wM = wid & 3, wN = wid >> 2;
    const int ghalf = blockIdx.x, tile = blockIdx.y, z = blockIdx.z;

    const bf16* wp = wpa;
    const float* bias = biasa;
    int slot = z, aimg = 0, xslot = 0, choff = 0;
    if (MODE == 0) { int dir = z >> 6; slot = z & 63; if (dir) { wp = wpb; bias = biasb; } }
    else if (MODE == 1) {
        int dir = z >> 3, b_ = z & 7;
        if (dir) wp = wpb;
        int teff = dir ? 7 - t : t;
        aimg = dir * 64 + teff * 8 + b_;
        xslot = teff * 8 + b_; choff = dir * 64;
    } else if (MODE == 3) { aimg = t * 8 + z; }

    const size_t actps = (size_t)PX * CIN;
    const bf16* aimg_p = act + (size_t)slot * 2 * actps;
    const size_t wps = (size_t)9 * 256 * CIN;
    const uint32_t su = smem_u32(sm);

    float acc[2][8][4];
#pragma unroll
    for (int a = 0; a < 2; a++)
#pragma unroll
        for (int n = 0; n < 8; n++)
#pragma unroll
            for (int c = 0; c < 4; c++) acc[a][n][c] = 0.f;

    const int NH = CIN / 64, NIT = 27 * NH;
    const int lrow = tid >> 1, seg = (tid & 1) * 64;
    const int gpxA = tile * 128 + lrow;

    auto issue = [&](int it) {
        int buf = it % 3;
        int term = it / (9 * NH), rem = it - term * (9 * NH);
        int k = rem / NH, half = rem - k * NH;
        int pa = (term == 1), pbw = (term == 2);
        int ys = (gpxA >> 5) + k / 3 - 1, xsv = (gpxA & 31) + k % 3 - 1;
        bool v = ((unsigned)ys < 32u) && ((unsigned)xsv < 32u);
        const char* asrc = (const char*)(aimg_p + (size_t)pa * actps +
                           (v ? (size_t)(ys * 32 + xsv) * CIN : (size_t)0) + half * 64) + seg;
        const char* bsrc = (const char*)(wp + (size_t)pbw * wps +
                           ((size_t)k * 256 + ghalf * 128 + lrow) * CIN + half * 64) + seg;
        uint32_t ab = su + buf * 32768 + lrow * 128;
        uint32_t bb_ = ab + 16384;
        uint32_t sz = v ? 16u : 0u;
#pragma unroll
        for (int j = 0; j < 4; j++) {
            uint32_t off = seg + j * 16;
            uint32_t swz = off ^ ((lrow & 7) << 4);
            cp16(ab + swz, asrc + j * 16, sz);
            cp16f(bb_ + swz, bsrc + j * 16);
        }
        cp_commit();
    };

    const int aro = (lane & 7) + 8 * ((lane >> 3) & 1), acs = (lane >> 4) & 1;
    const int bro = (lane & 7) + 8 * ((lane >> 4) & 1), bcs = (lane >> 3) & 1;

    issue(0);
    issue(1);
    for (int it = 0; it < NIT; it++) {
        if (it < NIT - 1) cp_wait1(); else cp_wait0();
        __syncthreads();
        if (it + 2 < NIT) issue(it + 2);
        uint32_t sa = su + (it % 3) * 32768, sb = sa + 16384;
#pragma unroll
        for (int s = 0; s < 4; s++) {
            uint32_t af[2][4];
#pragma unroll
            for (int mi = 0; mi < 2; mi++) {
                int row = wM * 32 + mi * 16 + aro;
                ldsm4(af[mi], sa + row * 128 + ((2 * s + acs) ^ (row & 7)) * 16);
            }
#pragma unroll
            for (int np = 0; np < 4; np++) {
                uint32_t bfr[4];
                int row = wN * 64 + np * 16 + bro;
                ldsm4(bfr, sb + row * 128 + ((2 * s + bcs) ^ (row & 7)) * 16);
#pragma unroll
                for (int mi = 0; mi < 2; mi++) {
                    mma16816(acc[mi][np * 2],     af[mi], bfr);
                    mma16816(acc[mi][np * 2 + 1], af[mi], bfr + 2);
                }
            }
        }
    }
    __syncthreads();

    float* st = (float*)sm;
    const int r0 = wM * 32 + (lane >> 2), c0 = wN * 64 + (lane & 3) * 2;
#pragma unroll
    for (int mi = 0; mi < 2; mi++)
#pragma unroll
        for (int ni = 0; ni < 8; ni++) {
            int r = r0 + mi * 16, c = c0 + ni * 8;
            *(float2*)(st + r * 130 + c)       = *(float2*)acc[mi][ni];
            *(float2*)(st + (r + 8) * 130 + c) = *(float2*)(acc[mi][ni] + 2);
        }
    __syncthreads();

    if (MODE == 0 || MODE == 2) {
        float* gout = gB + (size_t)z * PX * 256;
        float4 bq = *(const float4*)(bias + ghalf * 128 + lane * 4);
#pragma unroll 1
        for (int it = 0; it < 16; it++) {
            int px = wid + 8 * it;
            float2 a01 = *(float2*)(st + px * 130 + lane * 4);
            float2 a23 = *(float2*)(st + px * 130 + lane * 4 + 2);
            float4 o = { a01.x + bq.x, a01.y + bq.y, a23.x + bq.z, a23.y + bq.w };
            *(float4*)(gout + (size_t)(tile * 128 + px) * 256 + ghalf * 128 + lane * 4) = o;
        }
    } else {
        const int gch = ghalf * 32 + lane;
#pragma unroll 1
        for (int it = 0; it < 16; it++) {
            int px = wid + 8 * it;
            int gpx = tile * 128 + px;
            float2 a01 = *(float2*)(st + px * 130 + lane * 4);
            float2 a23 = *(float2*)(st + px * 130 + lane * 4 + 2);
            float4 g4 = *(const float4*)(gB + ((size_t)aimg * PX + gpx) * 256 + gch * 4);
            float i_ = a01.x + g4.x, f_ = a01.y + g4.y;
            float g_ = a23.x + g4.z, o_ = a23.y + g4.w;
            size_t ci = ((size_t)z * PX + gpx) * 64 + gch;
            float cp = cB[ci];
            float cn = sigf(f_) * cp + sigf(i_) * tanhf(g_);
            float hn = sigf(o_) * tanhf(cn);
            cB[ci] = cn;
            bf16 hh_ = __float2bfloat16(hn);
            bf16 hl_ = __float2bfloat16(hn - __bfloat162float(hh_));
            size_t hi_ = ((size_t)z * 2 * PX + gpx) * 64 + gch;
            hB[hi_] = hh_;
            hB[hi_ + (size_t)PX * 64] = hl_;
            if (MODE == 1) {
                size_t xb = ((size_t)(xslot * 2) * PX + gpx) * 128 + choff + gch;
                xsB[xb] = hh_;
                xsB[xb + (size_t)PX * 128] = hl_;
            }
            if (MODE == 3 && lastB)
                lastB[((size_t)z * PX + gpx) * 128 + gch] = hn;
        }
    }
}

// ===== L1 forward hh + fused cell, M-split: CTA 64px x 128 gates, 3 CTAs/SM =======
#define H64STAGE 24576
__global__ void __launch_bounds__(256, 3)
conv_hh64(const bf16* __restrict__ act, const bf16* __restrict__ wp,
          float* __restrict__ gB, float* __restrict__ cB,
          bf16* __restrict__ hB, float* __restrict__ lastB, int t)
{
    extern __shared__ __align__(16) char sm[];
    const int tid = threadIdx.x, lane = tid & 31, wid = tid >> 5;
    const int wM = wid & 1, wN = wid >> 1;        // warp: 32px x 32 gates
    const int ghalf = blockIdx.x, tile = blockIdx.y, z = blockIdx.z;
    const int aimg = t * 8 + z;

    const size_t actps = (size_t)PX * 64;
    const bf16* aimg_p = act + (size_t)z * 2 * actps;
    const size_t wps = (size_t)9 * 256 * 64;
    const uint32_t su = smem_u32(sm);

    float acc[2][4][4];
#pragma unroll
    for (int a = 0; a < 2; a++)
#pragma unroll
        for (int n = 0; n < 4; n++)
#pragma unroll
            for (int c = 0; c < 4; c++) acc[a][n][c] = 0.f;

    const int NIT = 27;
    const int gpxA = tile * 64 + (tid & 63);

    auto issue = [&](int it) {
        int buf = it % 3;
        int term = it / 9, k = it - term * 9;
        int pa = (term == 1), pbw = (term == 2);
        uint32_t base = su + buf * H64STAGE;
        if (tid < 64) {
            int r = tid;
            int ys = (gpxA >> 5) + k / 3 - 1, xsv = (gpxA & 31) + k % 3 - 1;
            bool v = ((unsigned)ys < 32u) && ((unsigned)xsv < 32u);
            const char* asrc = (const char*)(aimg_p + (size_t)pa * actps +
                               (v ? (size_t)(ys * 32 + xsv) * 64 : (size_t)0));
            uint32_t sz = v ? 16u : 0u;
            uint32_t dst = base + r * 128;
#pragma unroll
            for (int j = 0; j < 8; j++)
                cp16(dst + ((j ^ (r & 7)) * 16), asrc + j * 16, sz);
        } else if (tid < 192) {
            int r = tid - 64;
            const char* bsrc = (const char*)(wp + (size_t)pbw * wps +
                               ((size_t)k * 256 + ghalf * 128 + r) * 64);
            uint32_t dst = base + 8192 + r * 128;
#pragma unroll
            for (int j = 0; j < 8; j++)
                cp16f(dst + ((j ^ (r & 7)) * 16), bsrc + j * 16);
        }
        cp_commit();
    };

    const int aro = (lane & 7) + 8 * ((lane >> 3) & 1), acs = (lane >> 4) & 1;
    const int bro = (lane & 7) + 8 * ((lane >> 4) & 1), bcs = (lane >> 3) & 1;

    issue(0);
    issue(1);
    for (int it = 0; it < NIT; it++) {
        if (it < NIT - 1) cp_wait1(); else cp_wait0();
        __syncthreads();
        if (it + 2 < NIT) issue(it + 2);
        uint32_t sa = su + (it % 3) * H64STAGE, sb = sa + 8192;
#pragma unroll
        for (int s = 0; s < 4; s++) {
            uint32_t af[2][4];
#pragma unroll
            for (int mi = 0; mi < 2; mi++) {
                int row = wM * 32 + mi * 16 + aro;
                ldsm4(af[mi], sa + row * 128 + ((2 * s + acs) ^ (row & 7)) * 16);
            }
#pragma unroll
            for (int np = 0; np < 2; np++) {
                uint32_t bfr[4];
                int row = wN * 32 + np * 16 + bro;
                ldsm4(bfr, sb + row * 128 + ((2 * s + bcs) ^ (row & 7)) * 16);
#pragma unroll
                for (int mi = 0; mi < 2; mi++) {
                    mma16816(acc[mi][np * 2],     af[mi], bfr);
                    mma16816(acc[mi][np * 2 + 1], af[mi], bfr + 2);
                }
            }
        }
    }
    __syncthreads();

    // stage accs: 64 rows x 128 cols, stride 130 (float2 reads only)
    float* st = (float*)sm;
    const int r0 = wM * 32 + (lane >> 2), c0 = wN * 32 + (lane & 3) * 2;
#pragma unroll
    for (int mi = 0; mi < 2; mi++)
#pragma unroll
        for (int ni = 0; ni < 4; ni++) {
            int r = r0 + mi * 16, c = c0 + ni * 8;
            *(float2*)(st + r * 130 + c)       = *(float2*)acc[mi][ni];
            *(float2*)(st + (r + 8) * 130 + c) = *(float2*)(acc[mi][ni] + 2);
        }
    __syncthreads();

    const int gch = ghalf * 32 + lane;
#pragma unroll 1
    for (int it = 0; it < 8; it++) {
        int px = wid + 8 * it;
        int gpx = tile * 64 + px;
        float2 a01 = *(float2*)(st + px * 130 + lane * 4);
        float2 a23 = *(float2*)(st + px * 130 + lane * 4 + 2);
        float4 g4 = *(const float4*)(gB + ((size_t)aimg * PX + gpx) * 256 + gch * 4);
        float i_ = a01.x + g4.x, f_ = a01.y + g4.y;
        float g_ = a23.x + g4.z, o_ = a23.y + g4.w;
        size_t ci = ((size_t)z * PX + gpx) * 64 + gch;
        float cp = cB[ci];
        float cn = sigf(f_) * cp + sigf(i_) * tanhf(g_);
        float hn = sigf(o_) * tanhf(cn);
        cB[ci] = cn;
        bf16 hh_ = __float2bfloat16(hn);
        bf16 hl_ = __float2bfloat16(hn - __bfloat162float(hh_));
        size_t hi_ = ((size_t)z * 2 * PX + gpx) * 64 + gch;
        hB[hi_] = hh_;
        hB[hi_ + (size_t)PX * 64] = hl_;
        if (lastB)
            lastB[((size_t)z * PX + gpx) * 128 + gch] = hn;
    }
}

__global__ void cell_k(const float* __restrict__ gih, float* __restrict__ cB,
                       bf16* __restrict__ hB, bf16* __restrict__ xsB,
                       float* __restrict__ lastB, int mode, int lco, int n)
{
    int i = blockIdx.x * 256 + threadIdx.x;
    if (i >= n) return;
    int ch = i & 63, px = (i >> 6) & 1023, im = i >> 16;
    int gslot = im, xslot = 0, choff = 0;
    if (mode == 0) {
        int dir = im >> 3, b = im & 7;
        int teff = dir ? 7 : 0;
        gslot = dir * 64 + teff * 8 + b;
        xslot = teff * 8 + b; choff = dir * 64;
    }
    float4 g4 = *(const float4*)(gih + ((size_t)gslot * PX + px) * 256 + ch * 4);
    float cn = sigf(g4.x) * tanhf(g4.z);
    float hn = sigf(g4.w) * tanhf(cn);
    cB[i] = cn;
    bf16 hh_ = __float2bfloat16(hn);
    bf16 hl_ = __float2bfloat16(hn - __bfloat162float(hh_));
    size_t hb_ = ((size_t)im * 2 * PX + px) * 64 + ch;
    hB[hb_] = hh_;
    hB[hb_ + (size_t)PX * 64] = hl_;
    if (xsB) {
        size_t xb = ((size_t)(xslot * 2) * PX + px) * 128 + choff + ch;
        xsB[xb] = hh_;
        xsB[xb + (size_t)PX * 128] = hl_;
    }
    if (lastB) lastB[((size_t)im * PX + px) * 128 + lco + ch] = hn;
}

__global__ void __launch_bounds__(256) head_k(const float* __restrict__ last,
                                              const float* __restrict__ w,
                                              const float* __restrict__ bias,
                                              float* __restrict__ out)
{
    __shared__ float sw[8192];
    __shared__ float sb[64];
    int b = blockIdx.x, pb = blockIdx.y, tid = threadIdx.x;
    for (int i = tid; i < 8192; i += 256) sw[i] = w[i];
    if (tid < 64) sb[tid] = bias[tid];
    __syncthreads();
    int px = pb * 256 + tid;
    const float4* lrow = (const float4*)(last + ((size_t)b * PX + px) * 128);
    float4 lv[32];
#pragma unroll
    for (int j = 0; j < 32; j++) lv[j] = lrow[j];
#pragma unroll 1
    for (int o = 0; o < 64; o++) {
        const float4* wr = (const float4*)(sw + o * 128);
        float acc = sb[o];
#pragma unroll
        for (int j = 0; j < 32; j++) {
            float4 wv = wr[j];
            acc += lv[j].x * wv.x + lv[j].y * wv.y + lv[j].z * wv.z + lv[j].w * wv.w;
        }
        out[((size_t)b * 64 + o) * PX + px] = fmaxf(acc, 0.f);
    }
}

extern "C" void kernel_launch(void* const* d_in, const int* in_sizes, int n_in,
                              void* d_out, int out_size)
{
    const float* features = (const float*)d_in[0];
    const float* w_out = (const float*)d_in[17];
    const float* b_out = (const float*)d_in[18];
    float* out = (float*)d_out;

    bf16 *ft, *xs1, *hb, *wpk;
    float *cb, *g0, *g1, *last, *bc;
    cudaGetSymbolAddress((void**)&ft, g_ft);
    cudaGetSymbolAddress((void**)&xs1, g_xs1);
    cudaGetSymbolAddress((void**)&hb, g_hb);
    cudaGetSymbolAddress((void**)&cb, g_cb);
    cudaGetSymbolAddress((void**)&g0, g_g0);
    cudaGetSymbolAddress((void**)&g1, g_g1);
    cudaGetSymbolAddress((void**)&last, g_lastb);
    cudaGetSymbolAddress((void**)&wpk, g_wpk);
    cudaGetSymbolAddress((void**)&bc, g_bc);

    bf16* wih[4]; bf16* whh[3];
    for (int s = 0; s < 4; s++) wih[s] = wpk + (size_t)s * 589824;
    for (int s = 0; s < 3; s++) whh[s] = wpk + (size_t)4 * 589824 + (size_t)s * 294912;

    const int DSMEM = 3 * 32768;
    const int H64SMEM = 3 * H64STAGE;   // 73728 (epilogue needs 64*130*4 = 33280)
    cudaFuncSetAttribute(conv_hmma<128, 0>, cudaFuncAttributeMaxDynamicSharedMemorySize, DSMEM);
    cudaFuncSetAttribute(conv_hmma<128, 2>, cudaFuncAttributeMaxDynamicSharedMemorySize, DSMEM);
    cudaFuncSetAttribute(conv_hmma<64, 1>,  cudaFuncAttributeMaxDynamicSharedMemorySize, DSMEM);
    cudaFuncSetAttribute(conv_hh64, cudaFuncAttributeMaxDynamicSharedMemorySize, H64SMEM);

    setptr_k<<<1, 1>>>((const float*)d_in[1], (const float*)d_in[5],
                       (const float*)d_in[9], (const float*)d_in[13],
                       (const float*)d_in[2], (const float*)d_in[6],
                       (const float*)d_in[10],
                       (const float*)d_in[3], (const float*)d_in[7],
                       (const float*)d_in[11], (const float*)d_in[15],
                       (const float*)d_in[4], (const float*)d_in[8],
                       (const float*)d_in[12], (const float*)d_in[16]);
    repack_all<<<dim3(1152, 7), 256>>>(wpk, bc);
    feat_tr_k<<<dim3(64, 4, 4), 256>>>(features);

    const size_t CS = (size_t)PX * 64;
    const size_t HS = (size_t)2 * PX * 64;
    const size_t IMGZ = (size_t)PX * 256;
    const int N16 = 16 * PX * 64, N8 = 8 * PX * 64;

    // ===== layer 0 =====
    conv_hmma<128, 0><<<dim3(2, 8, 128), 256, DSMEM>>>(
        ft, wih[0], wih[1], bc, bc + 256, g0, nullptr, nullptr, nullptr, nullptr, 0);
    cell_k<<<N16 / 256, 256>>>(g0, cb, hb, xs1, nullptr, 0, 0, N16);
    for (int t = 1; t < TT; t++)
        conv_hmma<64, 1><<<dim3(2, 8, 16), 256, DSMEM>>>(
            hb, whh[0], whh[1], nullptr, nullptr, g0, cb, hb, xs1, nullptr, t);

    // ===== layer 1 ih: forward all t; reverse only t=7 =====
    conv_hmma<128, 2><<<dim3(2, 8, 64), 256, DSMEM>>>(
        xs1, wih[2], nullptr, bc + 512, nullptr, g1, nullptr, nullptr, nullptr, nullptr, 0);
    conv_hmma<128, 2><<<dim3(2, 8, 8), 256, DSMEM>>>(
        xs1 + (size_t)56 * 2 * PX * 128, wih[3], nullptr, bc + 768, nullptr,
        g1 + 64 * IMGZ, nullptr, nullptr, nullptr, nullptr, 0);

    cell_k<<<N8 / 256, 256>>>(g1 + 64 * IMGZ, cb + 16 * CS, hb + 16 * HS,
                              nullptr, last, 1, 64, N8);
    cell_k<<<N8 / 256, 256>>>(g1, cb + 24 * CS, hb + 24 * HS, nullptr, nullptr, 1, 0, N8);
    for (int t = 1; t < TT; t++)
        conv_hh64<<<dim3(2, 16, 8), 256, H64SMEM>>>(
            hb + 24 * HS, whh[2], g1, cb + 24 * CS, hb + 24 * HS,
            (t == TT - 1) ? last : nullptr, t);

    head_k<<<dim3(8, 4), 256>>>(last, w_out, b_out, out);
}